// round 12
// baseline (speedup 1.0000x reference)
#include <cuda_runtime.h>
#include <cuda_fp16.h>
#include <math.h>
#include <stdint.h>

#define N 8192
#define C 256
#define TM 128            // CTA M tile
#define TN 128            // N subtile
#define NSUB 8            // subtiles per CTA -> 1024 N per CTA
#define KC 64             // K chunk (64 halves = 128B rows)
#define NKC 4             // K chunks (K=256)
#define NIT (NSUB * NKC)  // 32 chunk iterations
#define NTHREADS 256
#define A_BYTES 65536     // 128 rows x 256 halves, 4 swizzled 16KB chunks
#define B_STAGE 16384     // 128 rows x 64 halves
#define B_OFF A_BYTES
#define SMEM_BYTES (A_BYTES + 2 * B_STAGE + 1024)   // 97.5 KB -> 2 CTAs/SM
#define PAIR_CAP (2u * 1024u * 1024u)
#define SCAP 1024
#define BNDF 0.25f

// ---------------- scratch (device globals; no allocation allowed) -----------
__device__ __half g_ah1[(size_t)N * C];    // v1 hi
__device__ __half g_ah2[(size_t)N * C];    // v2 hi
__device__ __half g_bh1[(size_t)N * C];    // p1 hi
__device__ __half g_bh2[(size_t)N * C];    // p2 hi
__device__ float g_iv1[N], g_iv2[N], g_ip1[N], g_ip2[N];      // inv norms
__device__ float g_nlv1[N], g_nlv2[N], g_nlp1[N], g_nlp2[N];  // ||lo|| per row
__device__ float g_diag1[N], g_diag2[N];
__device__ int   g_cnt1[N], g_cnt2[N];
__device__ unsigned int g_np;
__device__ uint32_t g_pairs[PAIR_CAP];

// ---------------- helpers ----------------------------------------------------
__device__ __forceinline__ uint32_t smem_u32(const void* p) {
    uint32_t a;
    asm("{ .reg .u64 t; cvta.to.shared.u64 t, %1; cvt.u32.u64 %0, t; }" : "=r"(a) : "l"(p));
    return a;
}
#define SWZ(x) ((x) ^ (((x) >> 3) & 0x70))

__device__ __forceinline__ void cp_async16(uint32_t sa, const void* g) {
    asm volatile("cp.async.cg.shared.global [%0], [%1], 16;" :: "r"(sa), "l"(g));
}
__device__ __forceinline__ void ldsm_x4(uint32_t* r, uint32_t addr) {
    asm volatile("ldmatrix.sync.aligned.m8n8.x4.shared.b16 {%0,%1,%2,%3}, [%4];"
                 : "=r"(r[0]), "=r"(r[1]), "=r"(r[2]), "=r"(r[3]) : "r"(addr));
}
__device__ __forceinline__ void mma16816(float* d, const uint32_t* a, const uint32_t* b) {
    asm volatile("mma.sync.aligned.m16n8k16.row.col.f32.f16.f16.f32 "
                 "{%0,%1,%2,%3}, {%4,%5,%6,%7}, {%8,%9}, {%0,%1,%2,%3};"
                 : "+f"(d[0]), "+f"(d[1]), "+f"(d[2]), "+f"(d[3])
                 : "r"(a[0]), "r"(a[1]), "r"(a[2]), "r"(a[3]), "r"(b[0]), "r"(b[1]));
}

// exact fp32 warp dot of normalized rows (raw * inv_norm)
__device__ __forceinline__ float warp_dot_norm(const float* __restrict__ ra,
                                               const float* __restrict__ rb,
                                               float ia, float ib, int lane) {
    const float4* pa = (const float4*)ra;
    const float4* pb = (const float4*)rb;
    float s = 0.0f;
    #pragma unroll
    for (int j = 0; j < 2; j++) {
        float4 a = pa[lane + j * 32];
        float4 b = pb[lane + j * 32];
        float ax = a.x * ia, ay = a.y * ia, az = a.z * ia, aw = a.w * ia;
        float bx = b.x * ib, by = b.y * ib, bz = b.z * ib, bw = b.w * ib;
        s = fmaf(ax, bx, fmaf(ay, by, fmaf(az, bz, fmaf(aw, bw, s))));
    }
    #pragma unroll
    for (int o = 16; o; o >>= 1) s += __shfl_xor_sync(0xffffffffu, s, o);
    return s;
}

// ---------------- kernel 1: warp-per-row normalize (no block barriers) ------
__global__ __launch_bounds__(256) void normalize_kernel(
    const float* __restrict__ v1, const float* __restrict__ v2,
    const float* __restrict__ p1, const float* __restrict__ p2)
{
    int warp = threadIdx.x >> 5;
    int lane = threadIdx.x & 31;
    int row = blockIdx.x * 8 + warp;
    size_t rbase = (size_t)row * C;

    float4 av[2], bv[2], cv[2], dv[2];
    #pragma unroll
    for (int j = 0; j < 2; j++) {
        av[j] = ((const float4*)(v1 + rbase))[lane + j * 32];
        bv[j] = ((const float4*)(v2 + rbase))[lane + j * 32];
        cv[j] = ((const float4*)(p1 + rbase))[lane + j * 32];
        dv[j] = ((const float4*)(p2 + rbase))[lane + j * 32];
    }

    float sa = 0, sb = 0, sc = 0, sd = 0;
    #pragma unroll
    for (int j = 0; j < 2; j++) {
        sa += av[j].x*av[j].x + av[j].y*av[j].y + av[j].z*av[j].z + av[j].w*av[j].w;
        sb += bv[j].x*bv[j].x + bv[j].y*bv[j].y + bv[j].z*bv[j].z + bv[j].w*bv[j].w;
        sc += cv[j].x*cv[j].x + cv[j].y*cv[j].y + cv[j].z*cv[j].z + cv[j].w*cv[j].w;
        sd += dv[j].x*dv[j].x + dv[j].y*dv[j].y + dv[j].z*dv[j].z + dv[j].w*dv[j].w;
    }
    #pragma unroll
    for (int o = 16; o; o >>= 1) {
        sa += __shfl_xor_sync(0xffffffffu, sa, o);
        sb += __shfl_xor_sync(0xffffffffu, sb, o);
        sc += __shfl_xor_sync(0xffffffffu, sc, o);
        sd += __shfl_xor_sync(0xffffffffu, sd, o);
    }
    float ia = 1.0f / fmaxf(sqrtf(sa), 1e-12f);
    float ib = 1.0f / fmaxf(sqrtf(sb), 1e-12f);
    float ic = 1.0f / fmaxf(sqrtf(sc), 1e-12f);
    float id = 1.0f / fmaxf(sqrtf(sd), 1e-12f);

    float la2 = 0, lb2 = 0, lc2 = 0, ld2 = 0;
    float dg1 = 0, dg2 = 0;
    #pragma unroll
    for (int j = 0; j < 2; j++) {
        float an[4] = {av[j].x*ia, av[j].y*ia, av[j].z*ia, av[j].w*ia};
        float bn[4] = {bv[j].x*ib, bv[j].y*ib, bv[j].z*ib, bv[j].w*ib};
        float cn[4] = {cv[j].x*ic, cv[j].y*ic, cv[j].z*ic, cv[j].w*ic};
        float dn[4] = {dv[j].x*id, dv[j].y*id, dv[j].z*id, dv[j].w*id};
        __half ha[4], hb[4], hc[4], hd[4];
        #pragma unroll
        for (int e = 0; e < 4; e++) {
            ha[e] = __float2half_rn(an[e]); hb[e] = __float2half_rn(bn[e]);
            hc[e] = __float2half_rn(cn[e]); hd[e] = __float2half_rn(dn[e]);
            float la = an[e] - __half2float(ha[e]); la2 += la * la;
            float lb = bn[e] - __half2float(hb[e]); lb2 += lb * lb;
            float lc = cn[e] - __half2float(hc[e]); lc2 += lc * lc;
            float ld = dn[e] - __half2float(hd[e]); ld2 += ld * ld;
            dg1 += an[e] * dn[e];
            dg2 += bn[e] * cn[e];
        }
        size_t eoff = rbase + (size_t)(lane + j * 32) * 4;
        *(uint2*)(g_ah1 + eoff) = *(uint2*)ha;
        *(uint2*)(g_ah2 + eoff) = *(uint2*)hb;
        *(uint2*)(g_bh1 + eoff) = *(uint2*)hc;
        *(uint2*)(g_bh2 + eoff) = *(uint2*)hd;
    }
    #pragma unroll
    for (int o = 16; o; o >>= 1) {
        la2 += __shfl_xor_sync(0xffffffffu, la2, o);
        lb2 += __shfl_xor_sync(0xffffffffu, lb2, o);
        lc2 += __shfl_xor_sync(0xffffffffu, lc2, o);
        ld2 += __shfl_xor_sync(0xffffffffu, ld2, o);
        dg1 += __shfl_xor_sync(0xffffffffu, dg1, o);
        dg2 += __shfl_xor_sync(0xffffffffu, dg2, o);
    }
    if (lane == 0) {
        g_iv1[row] = ia; g_iv2[row] = ib; g_ip1[row] = ic; g_ip2[row] = id;
        g_nlv1[row] = sqrtf(la2); g_nlv2[row] = sqrtf(lb2);
        g_nlp1[row] = sqrtf(lc2); g_nlp2[row] = sqrtf(ld2);
        g_diag1[row] = dg1; g_diag2[row] = dg2;
        g_cnt1[row] = 0;  g_cnt2[row] = 0;
        if (row == 0) g_np = 0;
    }
}

// ---------------- kernel 2: A-resident mma.sync GEMM + classify -------------
// CTA: 128(M) x 1024(N) as 8 subtiles, 256 threads (8 warps 2Mx4N),
// warp tile 64x32, K=256. A (64KB) once; B 2-stage (16KB). 2 CTAs/SM.
extern __shared__ char dynsmem[];

__global__ void __launch_bounds__(NTHREADS, 2) count_kernel()
{
    __shared__ int scnt[TM];
    __shared__ uint32_t s_pairs[SCAP];
    __shared__ unsigned int s_nu, s_base;

    const __half* __restrict__ A;
    const __half* __restrict__ B;
    const float* __restrict__ diag;
    const float* __restrict__ nla;
    const float* __restrict__ nlb;
    int* cnt;
    if (blockIdx.z == 0) { A = g_ah1; B = g_bh2; diag = g_diag1; nla = g_nlv1; nlb = g_nlp2; cnt = g_cnt1; }
    else                 { A = g_ah2; B = g_bh1; diag = g_diag2; nla = g_nlv2; nlb = g_nlp1; cnt = g_cnt2; }

    int tid = threadIdx.x;
    int wid = tid >> 5;
    int lane = tid & 31;
    int wm = wid >> 2;            // 0..1
    int wn = wid & 3;             // 0..3
    int row0 = blockIdx.y * TM;
    int col0 = blockIdx.x * (TN * NSUB);

    char* al = (char*)((((uintptr_t)dynsmem) + 1023) & ~(uintptr_t)1023);
    uint32_t sbase = smem_u32(al);

    if (tid < TM) scnt[tid] = 0;
    if (tid == 0) s_nu = 0;

    auto load_A_chunk = [&](int c) {
        #pragma unroll
        for (int i = 0; i < 4; i++) {
            int idx = tid + i * NTHREADS;
            int r = idx >> 3, kg = idx & 7;
            const __half* g = A + (size_t)(row0 + r) * C + c * KC + kg * 8;
            cp_async16(sbase + (uint32_t)c * 16384u + SWZ((uint32_t)(r * 128 + kg * 16)), g);
        }
        asm volatile("cp.async.commit_group;" ::: "memory");
    };

    auto load_B = [&](int g, int stage) {
        int nsub = g >> 2, kc = g & 3;
        uint32_t st = sbase + B_OFF + (uint32_t)stage * B_STAGE;
        #pragma unroll
        for (int i = 0; i < 4; i++) {
            int idx = tid + i * NTHREADS;
            int r = idx >> 3, kg = idx & 7;
            const __half* gp = B + (size_t)(col0 + nsub * TN + r) * C + kc * KC + kg * 8;
            cp_async16(st + SWZ((uint32_t)(r * 128 + kg * 16)), gp);
        }
        asm volatile("cp.async.commit_group;" ::: "memory");
    };

    // interleaved prologue: it0 only needs A0 + B0
    load_A_chunk(0);
    load_B(0, 0);
    load_A_chunk(1);
    load_A_chunk(2);
    load_A_chunk(3);
    load_B(1, 1);

    // per-row epilogue thresholds (8 rows/thread)
    int gid = lane >> 2, tig = lane & 3;
    float thrHi[8], thrLo[8];
    #pragma unroll
    for (int mi = 0; mi < 4; mi++)
        #pragma unroll
        for (int h = 0; h < 2; h++) {
            int grow = row0 + wm * 64 + mi * 16 + gid + h * 8;
            float dv = __ldg(&diag[grow]);
            float na = __ldg(&nla[grow]);
            thrHi[mi * 2 + h] = dv + BNDF * na + 4e-5f;
            thrLo[mi * 2 + h] = dv - BNDF * na - 4e-5f;
        }
    uint32_t dirbit = (uint32_t)blockIdx.z << 26;

    float acc[4][4][4];
    #pragma unroll
    for (int mi = 0; mi < 4; mi++)
        #pragma unroll
        for (int n8 = 0; n8 < 4; n8++)
            #pragma unroll
            for (int e = 0; e < 4; e++) acc[mi][n8][e] = 0.0f;

    #pragma unroll 1
    for (int it = 0; it < NIT; it++) {
        if (it == 0)           asm volatile("cp.async.wait_group 4;" ::: "memory");
        else if (it < NIT - 1) asm volatile("cp.async.wait_group 1;" ::: "memory");
        else                   asm volatile("cp.async.wait_group 0;" ::: "memory");
        __syncthreads();

        uint32_t stA = sbase + (uint32_t)(it & 3) * 16384u;
        uint32_t stB = sbase + B_OFF + (uint32_t)(it & 1) * B_STAGE;

        #pragma unroll
        for (int ks = 0; ks < 4; ks++) {
            uint32_t a[4][4], b[2][4];
            int kbA = ks * 32 + (lane >> 4) * 16;
            #pragma unroll
            for (int mi = 0; mi < 4; mi++) {
                int rowA = wm * 64 + mi * 16 + (lane & 15);
                uint32_t ad = stA + (uint32_t)(rowA * 128) +
                              (uint32_t)(kbA ^ ((rowA & 7) << 4));
                ldsm_x4(a[mi], ad);
            }
            int kbB = ks * 32 + ((lane >> 3) & 1) * 16;
            #pragma unroll
            for (int nb = 0; nb < 2; nb++) {
                int rowB = wn * 32 + nb * 16 + (lane & 7) + ((lane >> 4) & 1) * 8;
                uint32_t bd = stB + (uint32_t)(rowB * 128) +
                              (uint32_t)(kbB ^ ((rowB & 7) << 4));
                ldsm_x4(b[nb], bd);
            }
            #pragma unroll
            for (int mi = 0; mi < 4; mi++)
                #pragma unroll
                for (int n8 = 0; n8 < 4; n8++)
                    mma16816(acc[mi][n8], a[mi], &b[n8 >> 1][(n8 & 1) * 2]);
        }
        __syncthreads();                       // all reads of stB done

        if (it + 2 < NIT) load_B(it + 2, it & 1);

        if ((it & 3) == 3) {
            // ---- epilogue for subtile nsub ----
            int nsub = it >> 2;
            int cbase = col0 + nsub * TN + wn * 32;
            float bcol[8];
            #pragma unroll
            for (int n8 = 0; n8 < 4; n8++)
                #pragma unroll
                for (int e = 0; e < 2; e++)
                    bcol[n8 * 2 + e] = BNDF * __ldg(&nlb[cbase + n8 * 8 + tig * 2 + e]);

            #pragma unroll
            for (int mi = 0; mi < 4; mi++) {
                #pragma unroll
                for (int h = 0; h < 2; h++) {
                    int lrow = wm * 64 + mi * 16 + gid + h * 8;
                    int grow = row0 + lrow;
                    float hi = thrHi[mi * 2 + h], lo = thrLo[mi * 2 + h];
                    int cc = 0;
                    #pragma unroll
                    for (int n8 = 0; n8 < 4; n8++) {
                        #pragma unroll
                        for (int e = 0; e < 2; e++) {
                            float vv = acc[mi][n8][h * 2 + e];
                            float t = bcol[n8 * 2 + e];
                            int gcol = cbase + n8 * 8 + tig * 2 + e;
                            if (gcol != grow) {
                                if (vv - t > hi) cc++;
                                else if (vv + t > lo) {
                                    unsigned idx = atomicAdd(&s_nu, 1u);
                                    uint32_t rec = dirbit | ((uint32_t)grow << 13) | (uint32_t)gcol;
                                    if (idx < SCAP) s_pairs[idx] = rec;
                                    else {
                                        unsigned gi = atomicAdd(&g_np, 1u);
                                        if (gi < PAIR_CAP) g_pairs[gi] = rec;
                                    }
                                }
                            }
                            acc[mi][n8][h * 2 + e] = 0.0f;
                        }
                    }
                    if (cc) atomicAdd(&scnt[lrow], cc);
                }
            }
        }
    }

    __syncthreads();
    // bulk flush of smem pair buffer
    unsigned nu = s_nu < SCAP ? s_nu : SCAP;
    if (tid == 0 && nu) s_base = atomicAdd(&g_np, nu);
    __syncthreads();
    for (unsigned i = tid; i < nu; i += NTHREADS) {
        unsigned gi = s_base + i;
        if (gi < PAIR_CAP) g_pairs[gi] = s_pairs[i];
    }

    if (tid < TM) {
        int v = scnt[tid];
        if (v) atomicAdd(&cnt[row0 + tid], v);
    }
}

// ---------------- kernel 3: exact fp32 repair of uncertain pairs ------------
__global__ __launch_bounds__(256) void repair_kernel(
    const float* __restrict__ v1, const float* __restrict__ v2,
    const float* __restrict__ p1, const float* __restrict__ p2)
{
    int gw = (blockIdx.x * blockDim.x + threadIdx.x) >> 5;
    int lane = threadIdx.x & 31;
    int nwarps = (gridDim.x * blockDim.x) >> 5;
    unsigned np = g_np;
    if (np > PAIR_CAP) np = PAIR_CAP;

    for (unsigned i = gw; i < np; i += nwarps) {
        uint32_t e = g_pairs[i];
        int dir = (int)(e >> 26);
        int row = (int)((e >> 13) & 8191u);
        int col = (int)(e & 8191u);
        const float* ya = dir ? v2 : v1;
        const float* yb = dir ? p1 : p2;
        float ia = __ldg(dir ? &g_iv2[row] : &g_iv1[row]);
        float ib = __ldg(dir ? &g_ip1[col] : &g_ip2[col]);
        float s = warp_dot_norm(ya + (size_t)row * C, yb + (size_t)col * C, ia, ib, lane);
        float dv = __ldg(dir ? &g_diag2[row] : &g_diag1[row]);
        if (lane == 0 && s > dv) atomicAdd(dir ? &g_cnt2[row] : &g_cnt1[row], 1);
    }
}

// ---------------- kernel 4: final scalars (single block) --------------------
__global__ __launch_bounds__(1024) void finalize_kernel(float* __restrict__ out)
{
    int tid = threadIdx.x;

    double sd = 0.0, sp = 0.0;
    int r1 = 0, r5 = 0, r10 = 0;
    for (int i = tid; i < N; i += 1024) {
        sd += (double)g_diag1[i] + (double)g_diag2[i];
        int c1 = g_cnt1[i], c2 = g_cnt2[i];
        sp += (double)(c1 + c2);
        r1  += (c1 < 1)  + (c2 < 1);
        r5  += (c1 < 5)  + (c2 < 5);
        r10 += (c1 < 10) + (c2 < 10);
    }
    #pragma unroll
    for (int o = 16; o; o >>= 1) {
        sd  += __shfl_xor_sync(0xffffffffu, sd, o);
        sp  += __shfl_xor_sync(0xffffffffu, sp, o);
        r1  += __shfl_xor_sync(0xffffffffu, r1, o);
        r5  += __shfl_xor_sync(0xffffffffu, r5, o);
        r10 += __shfl_xor_sync(0xffffffffu, r10, o);
    }
    __shared__ double s_sd[32], s_sp[32];
    __shared__ int s_r1[32], s_r5[32], s_r10[32];
    int lane = tid & 31, w = tid >> 5;
    if (lane == 0) { s_sd[w] = sd; s_sp[w] = sp; s_r1[w] = r1; s_r5[w] = r5; s_r10[w] = r10; }
    __syncthreads();
    if (w == 0) {
        double tsd = s_sd[lane], tsp = s_sp[lane];
        int t1 = s_r1[lane], t5 = s_r5[lane], t10 = s_r10[lane];
        #pragma unroll
        for (int o = 16; o; o >>= 1) {
            tsd += __shfl_xor_sync(0xffffffffu, tsd, o);
            tsp += __shfl_xor_sync(0xffffffffu, tsp, o);
            t1  += __shfl_xor_sync(0xffffffffu, t1, o);
            t5  += __shfl_xor_sync(0xffffffffu, t5, o);
            t10 += __shfl_xor_sync(0xffffffffu, t10, o);
        }
        if (lane == 0) {
            double inv2N = 1.0 / (2.0 * (double)N);
            out[0] = (float)(-tsd * inv2N);
            out[1] = (float)((double)t1  * inv2N);
            out[2] = (float)((double)t5  * inv2N);
            out[3] = (float)((double)t10 * inv2N);
            out[4] = (float)((tsp + (double)N) * inv2N);
        }
    }
}

// ---------------- launch ------------------------------------------------------
extern "C" void kernel_launch(void* const* d_in, const int* in_sizes, int n_in,
                              void* d_out, int out_size)
{
    const float* v1 = (const float*)d_in[0];
    const float* v2 = (const float*)d_in[1];
    const float* p1 = (const float*)d_in[2];
    const float* p2 = (const float*)d_in[3];
    float* out = (float*)d_out;

    cudaFuncSetAttribute(count_kernel, cudaFuncAttributeMaxDynamicSharedMemorySize, SMEM_BYTES);

    normalize_kernel<<<N / 8, 256>>>(v1, v2, p1, p2);
    dim3 grid(N / (TN * NSUB), N / TM, 2);
    count_kernel<<<grid, NTHREADS, SMEM_BYTES>>>();
    repair_kernel<<<2048, 256>>>(v1, v2, p1, p2);
    finalize_kernel<<<1, 1024>>>(out);
}

// round 13
// speedup vs baseline: 1.0587x; 1.0587x over previous
#include <cuda_runtime.h>
#include <cuda_fp16.h>
#include <math.h>
#include <stdint.h>

#define N 8192
#define C 256
#define TM 128            // CTA M tile
#define TN 128            // N subtile
#define NSUB 4            // subtiles per CTA -> 512 N per CTA
#define KC 64             // K chunk (64 halves = 128B rows)
#define NKC 4             // K chunks (K=256)
#define NIT (NSUB * NKC)  // 16 chunk iterations
#define NTHREADS 256
#define A_BYTES 65536     // 128 rows x 256 halves, 4 swizzled 16KB chunks
#define B_STAGE 16384     // 128 rows x 64 halves
#define B_OFF A_BYTES
#define SMEM_BYTES (A_BYTES + 2 * B_STAGE + 1024)   // 97.5 KB -> 2 CTAs/SM
#define PAIR_CAP (2u * 1024u * 1024u)
#define SCAP 512
#define BNDF 0.25f

// ---------------- scratch (device globals; no allocation allowed) -----------
__device__ __half g_ah1[(size_t)N * C];    // v1 hi
__device__ __half g_ah2[(size_t)N * C];    // v2 hi
__device__ __half g_bh1[(size_t)N * C];    // p1 hi
__device__ __half g_bh2[(size_t)N * C];    // p2 hi
__device__ float g_iv1[N], g_iv2[N], g_ip1[N], g_ip2[N];      // inv norms
__device__ float g_nlv1[N], g_nlv2[N], g_nlp1[N], g_nlp2[N];  // ||lo|| per row
__device__ float g_diag1[N], g_diag2[N];
__device__ int   g_cnt1[N], g_cnt2[N];
__device__ unsigned int g_np;
__device__ uint32_t g_pairs[PAIR_CAP];

// ---------------- helpers ----------------------------------------------------
__device__ __forceinline__ uint32_t smem_u32(const void* p) {
    uint32_t a;
    asm("{ .reg .u64 t; cvta.to.shared.u64 t, %1; cvt.u32.u64 %0, t; }" : "=r"(a) : "l"(p));
    return a;
}
#define SWZ(x) ((x) ^ (((x) >> 3) & 0x70))

__device__ __forceinline__ void cp_async16(uint32_t sa, const void* g) {
    asm volatile("cp.async.cg.shared.global [%0], [%1], 16;" :: "r"(sa), "l"(g));
}
__device__ __forceinline__ void ldsm_x4(uint32_t* r, uint32_t addr) {
    asm volatile("ldmatrix.sync.aligned.m8n8.x4.shared.b16 {%0,%1,%2,%3}, [%4];"
                 : "=r"(r[0]), "=r"(r[1]), "=r"(r[2]), "=r"(r[3]) : "r"(addr));
}
__device__ __forceinline__ void mma16816(float* d, const uint32_t* a, const uint32_t* b) {
    asm volatile("mma.sync.aligned.m16n8k16.row.col.f32.f16.f16.f32 "
                 "{%0,%1,%2,%3}, {%4,%5,%6,%7}, {%8,%9}, {%0,%1,%2,%3};"
                 : "+f"(d[0]), "+f"(d[1]), "+f"(d[2]), "+f"(d[3])
                 : "r"(a[0]), "r"(a[1]), "r"(a[2]), "r"(a[3]), "r"(b[0]), "r"(b[1]));
}

// exact fp32 warp dot of normalized rows (raw * inv_norm)
__device__ __forceinline__ float warp_dot_norm(const float* __restrict__ ra,
                                               const float* __restrict__ rb,
                                               float ia, float ib, int lane) {
    const float4* pa = (const float4*)ra;
    const float4* pb = (const float4*)rb;
    float s = 0.0f;
    #pragma unroll
    for (int j = 0; j < 2; j++) {
        float4 a = pa[lane + j * 32];
        float4 b = pb[lane + j * 32];
        float ax = a.x * ia, ay = a.y * ia, az = a.z * ia, aw = a.w * ia;
        float bx = b.x * ib, by = b.y * ib, bz = b.z * ib, bw = b.w * ib;
        s = fmaf(ax, bx, fmaf(ay, by, fmaf(az, bz, fmaf(aw, bw, s))));
    }
    #pragma unroll
    for (int o = 16; o; o >>= 1) s += __shfl_xor_sync(0xffffffffu, s, o);
    return s;
}

// ---------------- kernel 1: warp-per-row normalize (no block barriers) ------
__global__ __launch_bounds__(256) void normalize_kernel(
    const float* __restrict__ v1, const float* __restrict__ v2,
    const float* __restrict__ p1, const float* __restrict__ p2)
{
    int warp = threadIdx.x >> 5;
    int lane = threadIdx.x & 31;
    int row = blockIdx.x * 8 + warp;
    size_t rbase = (size_t)row * C;

    float4 av[2], bv[2], cv[2], dv[2];
    #pragma unroll
    for (int j = 0; j < 2; j++) {
        av[j] = ((const float4*)(v1 + rbase))[lane + j * 32];
        bv[j] = ((const float4*)(v2 + rbase))[lane + j * 32];
        cv[j] = ((const float4*)(p1 + rbase))[lane + j * 32];
        dv[j] = ((const float4*)(p2 + rbase))[lane + j * 32];
    }

    float sa = 0, sb = 0, sc = 0, sd = 0;
    #pragma unroll
    for (int j = 0; j < 2; j++) {
        sa += av[j].x*av[j].x + av[j].y*av[j].y + av[j].z*av[j].z + av[j].w*av[j].w;
        sb += bv[j].x*bv[j].x + bv[j].y*bv[j].y + bv[j].z*bv[j].z + bv[j].w*bv[j].w;
        sc += cv[j].x*cv[j].x + cv[j].y*cv[j].y + cv[j].z*cv[j].z + cv[j].w*cv[j].w;
        sd += dv[j].x*dv[j].x + dv[j].y*dv[j].y + dv[j].z*dv[j].z + dv[j].w*dv[j].w;
    }
    #pragma unroll
    for (int o = 16; o; o >>= 1) {
        sa += __shfl_xor_sync(0xffffffffu, sa, o);
        sb += __shfl_xor_sync(0xffffffffu, sb, o);
        sc += __shfl_xor_sync(0xffffffffu, sc, o);
        sd += __shfl_xor_sync(0xffffffffu, sd, o);
    }
    float ia = 1.0f / fmaxf(sqrtf(sa), 1e-12f);
    float ib = 1.0f / fmaxf(sqrtf(sb), 1e-12f);
    float ic = 1.0f / fmaxf(sqrtf(sc), 1e-12f);
    float id = 1.0f / fmaxf(sqrtf(sd), 1e-12f);

    float la2 = 0, lb2 = 0, lc2 = 0, ld2 = 0;
    float dg1 = 0, dg2 = 0;
    #pragma unroll
    for (int j = 0; j < 2; j++) {
        float an[4] = {av[j].x*ia, av[j].y*ia, av[j].z*ia, av[j].w*ia};
        float bn[4] = {bv[j].x*ib, bv[j].y*ib, bv[j].z*ib, bv[j].w*ib};
        float cn[4] = {cv[j].x*ic, cv[j].y*ic, cv[j].z*ic, cv[j].w*ic};
        float dn[4] = {dv[j].x*id, dv[j].y*id, dv[j].z*id, dv[j].w*id};
        __half ha[4], hb[4], hc[4], hd[4];
        #pragma unroll
        for (int e = 0; e < 4; e++) {
            ha[e] = __float2half_rn(an[e]); hb[e] = __float2half_rn(bn[e]);
            hc[e] = __float2half_rn(cn[e]); hd[e] = __float2half_rn(dn[e]);
            float la = an[e] - __half2float(ha[e]); la2 += la * la;
            float lb = bn[e] - __half2float(hb[e]); lb2 += lb * lb;
            float lc = cn[e] - __half2float(hc[e]); lc2 += lc * lc;
            float ld = dn[e] - __half2float(hd[e]); ld2 += ld * ld;
            dg1 += an[e] * dn[e];
            dg2 += bn[e] * cn[e];
        }
        size_t eoff = rbase + (size_t)(lane + j * 32) * 4;
        *(uint2*)(g_ah1 + eoff) = *(uint2*)ha;
        *(uint2*)(g_ah2 + eoff) = *(uint2*)hb;
        *(uint2*)(g_bh1 + eoff) = *(uint2*)hc;
        *(uint2*)(g_bh2 + eoff) = *(uint2*)hd;
    }
    #pragma unroll
    for (int o = 16; o; o >>= 1) {
        la2 += __shfl_xor_sync(0xffffffffu, la2, o);
        lb2 += __shfl_xor_sync(0xffffffffu, lb2, o);
        lc2 += __shfl_xor_sync(0xffffffffu, lc2, o);
        ld2 += __shfl_xor_sync(0xffffffffu, ld2, o);
        dg1 += __shfl_xor_sync(0xffffffffu, dg1, o);
        dg2 += __shfl_xor_sync(0xffffffffu, dg2, o);
    }
    if (lane == 0) {
        g_iv1[row] = ia; g_iv2[row] = ib; g_ip1[row] = ic; g_ip2[row] = id;
        g_nlv1[row] = sqrtf(la2); g_nlv2[row] = sqrtf(lb2);
        g_nlp1[row] = sqrtf(lc2); g_nlp2[row] = sqrtf(ld2);
        g_diag1[row] = dg1; g_diag2[row] = dg2;
        g_cnt1[row] = 0;  g_cnt2[row] = 0;
        if (row == 0) g_np = 0;
    }
}

// ---------------- kernel 2: A-resident mma.sync GEMM + classify -------------
// CTA: 128(M) x 512(N) as 4 subtiles, 256 threads (8 warps 2Mx4N),
// warp tile 64x32, K=256. A (64KB) once; B 2-stage (16KB). 2 CTAs/SM.
// Single __syncthreads per iteration (CUTLASS-style multistage order):
//   wait -> sync -> issue load(it+1) into stage (it+1)&1 -> compute(it).
extern __shared__ char dynsmem[];

__global__ void __launch_bounds__(NTHREADS, 2) count_kernel()
{
    __shared__ int scnt[TM];
    __shared__ uint32_t s_pairs[SCAP];
    __shared__ unsigned int s_nu, s_base;

    const __half* __restrict__ A;
    const __half* __restrict__ B;
    const float* __restrict__ diag;
    const float* __restrict__ nla;
    const float* __restrict__ nlb;
    int* cnt;
    if (blockIdx.z == 0) { A = g_ah1; B = g_bh2; diag = g_diag1; nla = g_nlv1; nlb = g_nlp2; cnt = g_cnt1; }
    else                 { A = g_ah2; B = g_bh1; diag = g_diag2; nla = g_nlv2; nlb = g_nlp1; cnt = g_cnt2; }

    int tid = threadIdx.x;
    int wid = tid >> 5;
    int lane = tid & 31;
    int wm = wid >> 2;            // 0..1
    int wn = wid & 3;             // 0..3
    int row0 = blockIdx.y * TM;
    int col0 = blockIdx.x * (TN * NSUB);

    char* al = (char*)((((uintptr_t)dynsmem) + 1023) & ~(uintptr_t)1023);
    uint32_t sbase = smem_u32(al);

    if (tid < TM) scnt[tid] = 0;
    if (tid == 0) s_nu = 0;

    auto load_A_chunk = [&](int c) {
        #pragma unroll
        for (int i = 0; i < 4; i++) {
            int idx = tid + i * NTHREADS;
            int r = idx >> 3, kg = idx & 7;
            const __half* g = A + (size_t)(row0 + r) * C + c * KC + kg * 8;
            cp_async16(sbase + (uint32_t)c * 16384u + SWZ((uint32_t)(r * 128 + kg * 16)), g);
        }
        asm volatile("cp.async.commit_group;" ::: "memory");
    };

    auto load_B = [&](int g) {
        int nsub = g >> 2, kc = g & 3;
        uint32_t st = sbase + B_OFF + (uint32_t)(g & 1) * B_STAGE;
        #pragma unroll
        for (int i = 0; i < 4; i++) {
            int idx = tid + i * NTHREADS;
            int r = idx >> 3, kg = idx & 7;
            const __half* gp = B + (size_t)(col0 + nsub * TN + r) * C + kc * KC + kg * 8;
            cp_async16(st + SWZ((uint32_t)(r * 128 + kg * 16)), gp);
        }
        asm volatile("cp.async.commit_group;" ::: "memory");
    };

    // prologue: A0, B0 first (it0 needs only these), remaining A chunks behind
    load_A_chunk(0);
    load_B(0);
    load_A_chunk(1);
    load_A_chunk(2);
    load_A_chunk(3);

    // per-row epilogue thresholds (8 rows/thread)
    int gid = lane >> 2, tig = lane & 3;
    float thrHi[8], thrLo[8];
    #pragma unroll
    for (int mi = 0; mi < 4; mi++)
        #pragma unroll
        for (int h = 0; h < 2; h++) {
            int grow = row0 + wm * 64 + mi * 16 + gid + h * 8;
            float dv = __ldg(&diag[grow]);
            float na = __ldg(&nla[grow]);
            thrHi[mi * 2 + h] = dv + BNDF * na + 4e-5f;
            thrLo[mi * 2 + h] = dv - BNDF * na - 4e-5f;
        }
    uint32_t dirbit = (uint32_t)blockIdx.z << 26;

    float acc[4][4][4];
    #pragma unroll
    for (int mi = 0; mi < 4; mi++)
        #pragma unroll
        for (int n8 = 0; n8 < 4; n8++)
            #pragma unroll
            for (int e = 0; e < 4; e++) acc[mi][n8][e] = 0.0f;

    #pragma unroll 1
    for (int it = 0; it < NIT; it++) {
        // it0: groups in flight A0,B0,A1,A2,A3 -> wait_group 3 leaves A0,B0 done.
        // it>=1: single outstanding B group (issued one full iteration earlier).
        if (it == 0) asm volatile("cp.async.wait_group 3;" ::: "memory");
        else         asm volatile("cp.async.wait_group 0;" ::: "memory");
        __syncthreads();

        // issue next B load into stage (it+1)&1 — consumed at it-1, safe after sync
        if (it + 1 < NIT) load_B(it + 1);

        uint32_t stA = sbase + (uint32_t)(it & 3) * 16384u;
        uint32_t stB = sbase + B_OFF + (uint32_t)(it & 1) * B_STAGE;

        #pragma unroll
        for (int ks = 0; ks < 4; ks++) {
            uint32_t a[4][4], b[2][4];
            int kbA = ks * 32 + (lane >> 4) * 16;
            #pragma unroll
            for (int mi = 0; mi < 4; mi++) {
                int rowA = wm * 64 + mi * 16 + (lane & 15);
                uint32_t ad = stA + (uint32_t)(rowA * 128) +
                              (uint32_t)(kbA ^ ((rowA & 7) << 4));
                ldsm_x4(a[mi], ad);
            }
            int kbB = ks * 32 + ((lane >> 3) & 1) * 16;
            #pragma unroll
            for (int nb = 0; nb < 2; nb++) {
                int rowB = wn * 32 + nb * 16 + (lane & 7) + ((lane >> 4) & 1) * 8;
                uint32_t bd = stB + (uint32_t)(rowB * 128) +
                              (uint32_t)(kbB ^ ((rowB & 7) << 4));
                ldsm_x4(b[nb], bd);
            }
            #pragma unroll
            for (int mi = 0; mi < 4; mi++)
                #pragma unroll
                for (int n8 = 0; n8 < 4; n8++)
                    mma16816(acc[mi][n8], a[mi], &b[n8 >> 1][(n8 & 1) * 2]);
        }

        if ((it & 3) == 3) {
            // ---- epilogue for subtile nsub (registers only; no barrier) ----
            int nsub = it >> 2;
            int cbase = col0 + nsub * TN + wn * 32;
            float bcol[8];
            #pragma unroll
            for (int n8 = 0; n8 < 4; n8++)
                #pragma unroll
                for (int e = 0; e < 2; e++)
                    bcol[n8 * 2 + e] = BNDF * __ldg(&nlb[cbase + n8 * 8 + tig * 2 + e]);

            #pragma unroll
            for (int mi = 0; mi < 4; mi++) {
                #pragma unroll
                for (int h = 0; h < 2; h++) {
                    int lrow = wm * 64 + mi * 16 + gid + h * 8;
                    int grow = row0 + lrow;
                    float hi = thrHi[mi * 2 + h], lo = thrLo[mi * 2 + h];
                    int cc = 0;
                    #pragma unroll
                    for (int n8 = 0; n8 < 4; n8++) {
                        #pragma unroll
                        for (int e = 0; e < 2; e++) {
                            float vv = acc[mi][n8][h * 2 + e];
                            float t = bcol[n8 * 2 + e];
                            int gcol = cbase + n8 * 8 + tig * 2 + e;
                            if (gcol != grow) {
                                if (vv - t > hi) cc++;
                                else if (vv + t > lo) {
                                    unsigned idx = atomicAdd(&s_nu, 1u);
                                    uint32_t rec = dirbit | ((uint32_t)grow << 13) | (uint32_t)gcol;
                                    if (idx < SCAP) s_pairs[idx] = rec;
                                    else {
                                        unsigned gi = atomicAdd(&g_np, 1u);
                                        if (gi < PAIR_CAP) g_pairs[gi] = rec;
                                    }
                                }
                            }
                            acc[mi][n8][h * 2 + e] = 0.0f;
                        }
                    }
                    if (cc) atomicAdd(&scnt[lrow], cc);
                }
            }
        }
    }

    __syncthreads();
    // bulk flush of smem pair buffer
    unsigned nu = s_nu < SCAP ? s_nu : SCAP;
    if (tid == 0 && nu) s_base = atomicAdd(&g_np, nu);
    __syncthreads();
    for (unsigned i = tid; i < nu; i += NTHREADS) {
        unsigned gi = s_base + i;
        if (gi < PAIR_CAP) g_pairs[gi] = s_pairs[i];
    }

    if (tid < TM) {
        int v = scnt[tid];
        if (v) atomicAdd(&cnt[row0 + tid], v);
    }
}

// ---------------- kernel 3: exact fp32 repair of uncertain pairs ------------
__global__ __launch_bounds__(256) void repair_kernel(
    const float* __restrict__ v1, const float* __restrict__ v2,
    const float* __restrict__ p1, const float* __restrict__ p2)
{
    int gw = (blockIdx.x * blockDim.x + threadIdx.x) >> 5;
    int lane = threadIdx.x & 31;
    int nwarps = (gridDim.x * blockDim.x) >> 5;
    unsigned np = g_np;
    if (np > PAIR_CAP) np = PAIR_CAP;

    for (unsigned i = gw; i < np; i += nwarps) {
        uint32_t e = g_pairs[i];
        int dir = (int)(e >> 26);
        int row = (int)((e >> 13) & 8191u);
        int col = (int)(e & 8191u);
        const float* ya = dir ? v2 : v1;
        const float* yb = dir ? p1 : p2;
        float ia = __ldg(dir ? &g_iv2[row] : &g_iv1[row]);
        float ib = __ldg(dir ? &g_ip1[col] : &g_ip2[col]);
        float s = warp_dot_norm(ya + (size_t)row * C, yb + (size_t)col * C, ia, ib, lane);
        float dv = __ldg(dir ? &g_diag2[row] : &g_diag1[row]);
        if (lane == 0 && s > dv) atomicAdd(dir ? &g_cnt2[row] : &g_cnt1[row], 1);
    }
}

// ---------------- kernel 4: final scalars (single block) --------------------
__global__ __launch_bounds__(1024) void finalize_kernel(float* __restrict__ out)
{
    int tid = threadIdx.x;

    double sd = 0.0, sp = 0.0;
    int r1 = 0, r5 = 0, r10 = 0;
    for (int i = tid; i < N; i += 1024) {
        sd += (double)g_diag1[i] + (double)g_diag2[i];
        int c1 = g_cnt1[i], c2 = g_cnt2[i];
        sp += (double)(c1 + c2);
        r1  += (c1 < 1)  + (c2 < 1);
        r5  += (c1 < 5)  + (c2 < 5);
        r10 += (c1 < 10) + (c2 < 10);
    }
    #pragma unroll
    for (int o = 16; o; o >>= 1) {
        sd  += __shfl_xor_sync(0xffffffffu, sd, o);
        sp  += __shfl_xor_sync(0xffffffffu, sp, o);
        r1  += __shfl_xor_sync(0xffffffffu, r1, o);
        r5  += __shfl_xor_sync(0xffffffffu, r5, o);
        r10 += __shfl_xor_sync(0xffffffffu, r10, o);
    }
    __shared__ double s_sd[32], s_sp[32];
    __shared__ int s_r1[32], s_r5[32], s_r10[32];
    int lane = tid & 31, w = tid >> 5;
    if (lane == 0) { s_sd[w] = sd; s_sp[w] = sp; s_r1[w] = r1; s_r5[w] = r5; s_r10[w] = r10; }
    __syncthreads();
    if (w == 0) {
        double tsd = s_sd[lane], tsp = s_sp[lane];
        int t1 = s_r1[lane], t5 = s_r5[lane], t10 = s_r10[lane];
        #pragma unroll
        for (int o = 16; o; o >>= 1) {
            tsd += __shfl_xor_sync(0xffffffffu, tsd, o);
            tsp += __shfl_xor_sync(0xffffffffu, tsp, o);
            t1  += __shfl_xor_sync(0xffffffffu, t1, o);
            t5  += __shfl_xor_sync(0xffffffffu, t5, o);
            t10 += __shfl_xor_sync(0xffffffffu, t10, o);
        }
        if (lane == 0) {
            double inv2N = 1.0 / (2.0 * (double)N);
            out[0] = (float)(-tsd * inv2N);
            out[1] = (float)((double)t1  * inv2N);
            out[2] = (float)((double)t5  * inv2N);
            out[3] = (float)((double)t10 * inv2N);
            out[4] = (float)((tsp + (double)N) * inv2N);
        }
    }
}

// ---------------- launch ------------------------------------------------------
extern "C" void kernel_launch(void* const* d_in, const int* in_sizes, int n_in,
                              void* d_out, int out_size)
{
    const float* v1 = (const float*)d_in[0];
    const float* v2 = (const float*)d_in[1];
    const float* p1 = (const float*)d_in[2];
    const float* p2 = (const float*)d_in[3];
    float* out = (float*)d_out;

    cudaFuncSetAttribute(count_kernel, cudaFuncAttributeMaxDynamicSharedMemorySize, SMEM_BYTES);

    normalize_kernel<<<N / 8, 256>>>(v1, v2, p1, p2);
    dim3 grid(N / (TN * NSUB), N / TM, 2);
    count_kernel<<<grid, NTHREADS, SMEM_BYTES>>>();
    repair_kernel<<<2048, 256>>>(v1, v2, p1, p2);
    finalize_kernel<<<1, 1024>>>(out);
}